// round 4
// baseline (speedup 1.0000x reference)
#include <cuda_runtime.h>
#include <cuda_bf16.h>
#include <math.h>
#include <stdint.h>
#include <mma.h>

using namespace nvcuda;

#define D 128
#define MAXN 50000
#define LDM 136   // padded leading dim (multiple of 4 floats = 16B)

// ---------------- scratch ----------------
__device__ float g_h[MAXN * D];
__device__ float g_m[MAXN * D];
__device__ float g_agg[MAXN * D];
__device__ float g_gi[MAXN * 3 * D];
__device__ float g_gh[MAXN * 3 * D];
__device__ float g_convT[2 * D * D];   // conv_w transposed -> B operand [n][k]

// ================= wmma tf32 GEMM =================
// C[N x M] = A[N x 128] @ B^T ; B is [M rows, 128 cols] K-major (row-major).
// CTA tile 128x128, 256 threads (8 warps as 2m x 4n), warp tile 64x32.
#define SMEM_FLOATS (2 * 128 * LDM)

__global__ __launch_bounds__(256, 1)
void gemm_wmma(const float* __restrict__ A, const float* __restrict__ Bw,
               float* __restrict__ C, int N, int M) {
    extern __shared__ float smem[];
    float* As = smem;               // [128][LDM]
    float* Bs = smem + 128 * LDM;   // [128][LDM] rows = output cols (n), cols = k

    int tid = threadIdx.x;
    int w = tid >> 5;
    int block_row = blockIdx.y * 128;
    int block_col = blockIdx.x * 128;

    // ---- stage tiles into smem, converting to tf32 precision ----
    {
        int r = tid >> 1;             // 0..127
        int kb = (tid & 1) * 64;      // 0 or 64
        bool va = (block_row + r) < N;
        const float4* arow = (const float4*)(A + (size_t)(block_row + r) * 128 + kb);
        const float4* brow = (const float4*)(Bw + (size_t)(block_col + r) * 128 + kb);
#pragma unroll
        for (int i = 0; i < 16; i++) {
            float4 x = va ? arow[i] : make_float4(0.f, 0.f, 0.f, 0.f);
            x.x = wmma::__float_to_tf32(x.x);
            x.y = wmma::__float_to_tf32(x.y);
            x.z = wmma::__float_to_tf32(x.z);
            x.w = wmma::__float_to_tf32(x.w);
            *(float4*)&As[r * LDM + kb + i * 4] = x;
            float4 y = brow[i];
            y.x = wmma::__float_to_tf32(y.x);
            y.y = wmma::__float_to_tf32(y.y);
            y.z = wmma::__float_to_tf32(y.z);
            y.w = wmma::__float_to_tf32(y.w);
            *(float4*)&Bs[r * LDM + kb + i * 4] = y;
        }
    }
    __syncthreads();

    int wm = w >> 2;   // 0..1
    int wn = w & 3;    // 0..3

    wmma::fragment<wmma::accumulator, 16, 16, 8, float> acc[4][2];
#pragma unroll
    for (int i = 0; i < 4; i++)
#pragma unroll
        for (int j = 0; j < 2; j++)
            wmma::fill_fragment(acc[i][j], 0.0f);

#pragma unroll 4
    for (int k0 = 0; k0 < 128; k0 += 8) {
        wmma::fragment<wmma::matrix_a, 16, 16, 8, wmma::precision::tf32,
                       wmma::row_major> af[4];
        wmma::fragment<wmma::matrix_b, 16, 16, 8, wmma::precision::tf32,
                       wmma::col_major> bf[2];
#pragma unroll
        for (int i = 0; i < 4; i++)
            wmma::load_matrix_sync(af[i], &As[(wm * 64 + i * 16) * LDM + k0], LDM);
#pragma unroll
        for (int j = 0; j < 2; j++)
            wmma::load_matrix_sync(bf[j], &Bs[(wn * 32 + j * 16) * LDM + k0], LDM);
#pragma unroll
        for (int i = 0; i < 4; i++)
#pragma unroll
            for (int j = 0; j < 2; j++)
                wmma::mma_sync(acc[i][j], af[i], bf[j], acc[i][j]);
    }

    __syncthreads();   // done reading As/Bs; reuse As as C staging [128][LDM]

#pragma unroll
    for (int i = 0; i < 4; i++)
#pragma unroll
        for (int j = 0; j < 2; j++)
            wmma::store_matrix_sync(&As[(wm * 64 + i * 16) * LDM + wn * 32 + j * 16],
                                    acc[i][j], LDM, wmma::mem_row_major);
    __syncthreads();

    // guarded vectorized store to global
    {
        int r = tid >> 1;
        int cb = (tid & 1) * 64;
        if (block_row + r < N) {
            float* crow = C + (size_t)(block_row + r) * M + block_col + cb;
#pragma unroll
            for (int i = 0; i < 16; i++)
                *(float4*)(crow + i * 4) = *(float4*)&As[r * LDM + cb + i * 4];
        }
    }
}

// ---------------- conv weight transpose: BT[l][n][k] = W[l][k][n] ----------------
__global__ void conv_transpose_kernel(const float* __restrict__ W, float* __restrict__ BT) {
    int idx = blockIdx.x * blockDim.x + threadIdx.x;
    if (idx >= 2 * D * D) return;
    int l = idx / (D * D);
    int rem = idx % (D * D);
    int k = rem / D;
    int n = rem % D;
    BT[(size_t)l * D * D + (size_t)n * D + k] = W[idx];
}

// ---------------- gather: h = embed[node_ids] ----------------
__global__ void gather_kernel(const int* __restrict__ node_ids,
                              const float4* __restrict__ embed4,
                              float4* __restrict__ h4, int N) {
    int idx = blockIdx.x * blockDim.x + threadIdx.x;
    if (idx >= N * 32) return;
    int n = idx >> 5;
    int c = idx & 31;
    int id = node_ids[n];
    h4[(size_t)n * 32 + c] = embed4[(size_t)id * 32 + c];
}

// ---------------- edge scatter: agg[dst] += m[src], one warp per edge ----------------
__global__ void scatter_kernel(const float4* __restrict__ m4,
                               const int* __restrict__ src,
                               const int* __restrict__ dst,
                               float* __restrict__ agg, int E) {
    int e = blockIdx.x * (blockDim.x >> 5) + (threadIdx.x >> 5);
    int lane = threadIdx.x & 31;
    if (e >= E) return;
    int s = __ldg(&src[e]);
    int d = __ldg(&dst[e]);
    float4 v = m4[(size_t)s * 32 + lane];
    float* p = agg + (size_t)d * D + lane * 4;
    asm volatile("red.global.add.v4.f32 [%0], {%1, %2, %3, %4};"
                 :: "l"(p), "f"(v.x), "f"(v.y), "f"(v.z), "f"(v.w) : "memory");
}

// ---------------- GRU gate fusion (vectorized, biases folded in here) ----------------
__global__ void gru_kernel(const float4* __restrict__ gi4,
                           const float4* __restrict__ gh4,
                           const float4* __restrict__ bih4,
                           const float4* __restrict__ bhh4,
                           float4* __restrict__ h4, int total4) {
    int idx = blockIdx.x * blockDim.x + threadIdx.x;
    if (idx >= total4) return;
    int n = idx >> 5;
    int c = idx & 31;
    const float4* gin = gi4 + (size_t)n * 96;
    const float4* ghn = gh4 + (size_t)n * 96;
    float4 ir = gin[c], iz = gin[c + 32], in_ = gin[c + 64];
    float4 hr = ghn[c], hz = ghn[c + 32], hn = ghn[c + 64];
    float4 bir = bih4[c], biz = bih4[c + 32], bin = bih4[c + 64];
    float4 bhr = bhh4[c], bhz = bhh4[c + 32], bhn = bhh4[c + 64];
    float4 h = h4[idx];
    float4 o;
#define GRU1(X)                                                                 \
    {                                                                           \
        float r = 1.0f / (1.0f + __expf(-(ir.X + bir.X + hr.X + bhr.X)));       \
        float z = 1.0f / (1.0f + __expf(-(iz.X + biz.X + hz.X + bhz.X)));       \
        float nn = tanhf(in_.X + bin.X + r * (hn.X + bhn.X));                   \
        o.X = (1.0f - z) * nn + z * h.X;                                        \
    }
    GRU1(x) GRU1(y) GRU1(z) GRU1(w)
#undef GRU1
    h4[idx] = o;
}

// ---------------- per-graph mean pool (batch sorted) ----------------
__device__ __forceinline__ int lower_bound_dev(const int* a, int n, int key) {
    int lo = 0, hi = n;
    while (lo < hi) {
        int mid = (lo + hi) >> 1;
        if (a[mid] < key) lo = mid + 1; else hi = mid;
    }
    return lo;
}

__global__ void pool_kernel(const float* __restrict__ h,
                            const int* __restrict__ batch,
                            float* __restrict__ out, int N) {
    int g = blockIdx.x;
    int tid = threadIdx.x;
    int sub = tid >> 7;
    int d = tid & 127;
    __shared__ int s_lo, s_hi;
    __shared__ float sbuf[4][128];
    if (tid == 0) {
        s_lo = lower_bound_dev(batch, N, g);
        s_hi = lower_bound_dev(batch, N, g + 1);
    }
    __syncthreads();
    int lo = s_lo, hi = s_hi;
    float acc = 0.0f;
    for (int n = lo + sub; n < hi; n += 4)
        acc += h[(size_t)n * D + d];
    sbuf[sub][d] = acc;
    __syncthreads();
    if (sub == 0) {
        float total = sbuf[0][d] + sbuf[1][d] + sbuf[2][d] + sbuf[3][d];
        float cnt = (float)(hi - lo);
        out[(size_t)g * D + d] = total / fmaxf(cnt, 1.0f);
    }
}

// ---------------- launch ----------------
extern "C" void kernel_launch(void* const* d_in, const int* in_sizes, int n_in,
                              void* d_out, int out_size) {
    const int* node_ids = (const int*)d_in[0];
    const int* edge_index = (const int*)d_in[1];
    const int* batch = (const int*)d_in[2];
    const float* embed = (const float*)d_in[4];
    const float* conv_w = (const float*)d_in[5];
    const float* w_ih = (const float*)d_in[6];
    const float* w_hh = (const float*)d_in[7];
    const float* b_ih = (const float*)d_in[8];
    const float* b_hh = (const float*)d_in[9];
    float* out = (float*)d_out;

    int N = in_sizes[0];
    int E = in_sizes[1] / 2;
    int G = out_size / D;
    const int* src = edge_index;
    const int* dst = edge_index + E;

    float *h, *m, *agg, *gi, *gh, *convT;
    cudaGetSymbolAddress((void**)&h, g_h);
    cudaGetSymbolAddress((void**)&m, g_m);
    cudaGetSymbolAddress((void**)&agg, g_agg);
    cudaGetSymbolAddress((void**)&gi, g_gi);
    cudaGetSymbolAddress((void**)&gh, g_gh);
    cudaGetSymbolAddress((void**)&convT, g_convT);

    static int smem_set = 0;
    if (!smem_set) {
        cudaFuncSetAttribute(gemm_wmma, cudaFuncAttributeMaxDynamicSharedMemorySize,
                             SMEM_FLOATS * (int)sizeof(float));
        smem_set = 1;
    }

    conv_transpose_kernel<<<(2 * D * D + 255) / 256, 256>>>(conv_w, convT);
    gather_kernel<<<(N * 32 + 255) / 256, 256>>>(node_ids, (const float4*)embed,
                                                 (float4*)h, N);

    int rowBlocks = (N + 127) / 128;
    size_t smemBytes = SMEM_FLOATS * sizeof(float);

    for (int layer = 0; layer < 2; layer++) {
        // m = h @ conv_w[layer]  (B = convT[layer], [128x128] K-major)
        gemm_wmma<<<dim3(1, rowBlocks), 256, smemBytes>>>(
            h, convT + (size_t)layer * D * D, m, N, D);

        cudaMemsetAsync(agg, 0, (size_t)N * D * sizeof(float), 0);

        {
            int warpsPerBlock = 8;
            int blocks = (E + warpsPerBlock - 1) / warpsPerBlock;
            scatter_kernel<<<blocks, warpsPerBlock * 32>>>((const float4*)m, src, dst,
                                                           agg, E);
        }

        // gi = agg @ w_ih^T ; gh = h @ w_hh^T   (biases folded into gru_kernel)
        gemm_wmma<<<dim3(3, rowBlocks), 256, smemBytes>>>(agg, w_ih, gi, N, 3 * D);
        gemm_wmma<<<dim3(3, rowBlocks), 256, smemBytes>>>(h, w_hh, gh, N, 3 * D);

        gru_kernel<<<(N * 32 + 255) / 256, 256>>>((const float4*)gi,
                                                  (const float4*)gh,
                                                  (const float4*)b_ih,
                                                  (const float4*)b_hh,
                                                  (float4*)h, N * 32);
    }

    pool_kernel<<<G, 512>>>(h, batch, out, N);
}

// round 5
// speedup vs baseline: 1.1079x; 1.1079x over previous
#include <cuda_runtime.h>
#include <cuda_bf16.h>
#include <math.h>
#include <stdint.h>
#include <mma.h>

using namespace nvcuda;

#define D 128
#define MAXN 50000
#define NPAD 50048           // 391 * 128, row-padded so GEMM C stores need no guard
#define LDM 136              // padded smem leading dim

// ---------------- scratch ----------------
__device__ float g_h[NPAD * D];
__device__ float g_m[NPAD * D];
__device__ float g_agg[NPAD * D];
__device__ float g_gi[NPAD * 3 * D];
__device__ float g_gh[NPAD * 3 * D];
__device__ float g_convT[2 * D * D];   // conv_w transposed -> B operand [n][k]

// ================= wmma tf32 GEMM, software-pipelined =================
// C[N x M] = A[N x 128] @ B^T ; B is [M rows, 128 cols] K-major.
// CTA tile 128x128, 256 threads (8 warps as 2m x 4n), warp tile 64x32.
// C rows are UNGUARDED (buffers padded to NPAD); A rows ≥ N are zero-filled.
#define SMEM_FLOATS (2 * 128 * LDM)

__global__ __launch_bounds__(256, 1)
void gemm_wmma(const float* __restrict__ A, const float* __restrict__ Bw,
               float* __restrict__ C, int N, int M) {
    extern __shared__ float smem[];
    float* As = smem;               // [128][LDM]
    float* Bs = smem + 128 * LDM;   // [128][LDM], rows = output cols (n)

    int tid = threadIdx.x;
    int w = tid >> 5;
    int block_row = blockIdx.y * 128;
    int block_col = blockIdx.x * 128;

    // ---- stage tiles (fp32 -> tf32) ----
    {
        int r = tid >> 1;
        int kb = (tid & 1) * 64;
        bool va = (block_row + r) < N;
        const float4* arow = (const float4*)(A + (size_t)(block_row + r) * 128 + kb);
        const float4* brow = (const float4*)(Bw + (size_t)(block_col + r) * 128 + kb);
#pragma unroll
        for (int i = 0; i < 16; i++) {
            float4 x = va ? arow[i] : make_float4(0.f, 0.f, 0.f, 0.f);
            x.x = wmma::__float_to_tf32(x.x);
            x.y = wmma::__float_to_tf32(x.y);
            x.z = wmma::__float_to_tf32(x.z);
            x.w = wmma::__float_to_tf32(x.w);
            *(float4*)&As[r * LDM + kb + i * 4] = x;
            float4 y = brow[i];
            y.x = wmma::__float_to_tf32(y.x);
            y.y = wmma::__float_to_tf32(y.y);
            y.z = wmma::__float_to_tf32(y.z);
            y.w = wmma::__float_to_tf32(y.w);
            *(float4*)&Bs[r * LDM + kb + i * 4] = y;
        }
    }
    __syncthreads();

    int wm = w >> 2;   // 0..1
    int wn = w & 3;    // 0..3
    const float* aBase = &As[wm * 64 * LDM];
    const float* bBase = &Bs[wn * 32 * LDM];

    wmma::fragment<wmma::accumulator, 16, 16, 8, float> acc[4][2];
#pragma unroll
    for (int i = 0; i < 4; i++)
#pragma unroll
        for (int j = 0; j < 2; j++)
            wmma::fill_fragment(acc[i][j], 0.0f);

    // double-buffered fragments; fully unrolled so indices are compile-time
    wmma::fragment<wmma::matrix_a, 16, 16, 8, wmma::precision::tf32,
                   wmma::row_major> af[2][4];
    wmma::fragment<wmma::matrix_b, 16, 16, 8, wmma::precision::tf32,
                   wmma::col_major> bf[2][2];

#pragma unroll
    for (int i = 0; i < 4; i++)
        wmma::load_matrix_sync(af[0][i], aBase + (i * 16) * LDM, LDM);
#pragma unroll
    for (int j = 0; j < 2; j++)
        wmma::load_matrix_sync(bf[0][j], bBase + (j * 16) * LDM, LDM);

#pragma unroll
    for (int s = 0; s < 16; s++) {
        const int cur = s & 1;
        const int nxt = cur ^ 1;
        if (s < 15) {
            const int k = (s + 1) * 8;
#pragma unroll
            for (int i = 0; i < 4; i++)
                wmma::load_matrix_sync(af[nxt][i], aBase + (i * 16) * LDM + k, LDM);
#pragma unroll
            for (int j = 0; j < 2; j++)
                wmma::load_matrix_sync(bf[nxt][j], bBase + (j * 16) * LDM + k, LDM);
        }
#pragma unroll
        for (int i = 0; i < 4; i++)
#pragma unroll
            for (int j = 0; j < 2; j++)
                wmma::mma_sync(acc[i][j], af[cur][i], bf[cur][j], acc[i][j]);
    }

    // ---- direct store (C padded; no guard, no smem round-trip) ----
    float* cw = C + (size_t)(block_row + wm * 64) * M + block_col + wn * 32;
#pragma unroll
    for (int i = 0; i < 4; i++)
#pragma unroll
        for (int j = 0; j < 2; j++)
            wmma::store_matrix_sync(cw + (size_t)(i * 16) * M + j * 16, acc[i][j],
                                    M, wmma::mem_row_major);
}

// ---------------- conv weight transpose: BT[l][n][k] = W[l][k][n] ----------------
__global__ void conv_transpose_kernel(const float* __restrict__ W, float* __restrict__ BT) {
    int idx = blockIdx.x * blockDim.x + threadIdx.x;
    if (idx >= 2 * D * D) return;
    int l = idx / (D * D);
    int rem = idx % (D * D);
    int k = rem / D;
    int n = rem % D;
    BT[(size_t)l * D * D + (size_t)n * D + k] = W[idx];
}

// ---------------- gather: h = embed[node_ids]; also zero agg ----------------
__global__ void gather_kernel(const int* __restrict__ node_ids,
                              const float4* __restrict__ embed4,
                              float4* __restrict__ h4,
                              float4* __restrict__ agg4, int N) {
    int idx = blockIdx.x * blockDim.x + threadIdx.x;
    if (idx >= N * 32) return;
    int n = idx >> 5;
    int c = idx & 31;
    int id = node_ids[n];
    h4[(size_t)n * 32 + c] = embed4[(size_t)id * 32 + c];
    agg4[idx] = make_float4(0.f, 0.f, 0.f, 0.f);
}

// ---------------- edge scatter: agg[dst] += m[src], one warp per edge ----------------
__global__ void scatter_kernel(const float4* __restrict__ m4,
                               const int* __restrict__ src,
                               const int* __restrict__ dst,
                               float* __restrict__ agg, int E) {
    int e = blockIdx.x * (blockDim.x >> 5) + (threadIdx.x >> 5);
    int lane = threadIdx.x & 31;
    if (e >= E) return;
    int s = __ldg(&src[e]);
    int d = __ldg(&dst[e]);
    float4 v = m4[(size_t)s * 32 + lane];
    float* p = agg + (size_t)d * D + lane * 4;
    asm volatile("red.global.add.v4.f32 [%0], {%1, %2, %3, %4};"
                 :: "l"(p), "f"(v.x), "f"(v.y), "f"(v.z), "f"(v.w) : "memory");
}

// ---------------- GRU gate fusion; optionally zero agg for next layer ----------------
__global__ void gru_kernel(const float4* __restrict__ gi4,
                           const float4* __restrict__ gh4,
                           const float4* __restrict__ bih4,
                           const float4* __restrict__ bhh4,
                           float4* __restrict__ h4,
                           float4* __restrict__ agg4,
                           int total4, int zero_agg) {
    int idx = blockIdx.x * blockDim.x + threadIdx.x;
    if (idx >= total4) return;
    int n = idx >> 5;
    int c = idx & 31;
    const float4* gin = gi4 + (size_t)n * 96;
    const float4* ghn = gh4 + (size_t)n * 96;
    float4 ir = gin[c], iz = gin[c + 32], in_ = gin[c + 64];
    float4 hr = ghn[c], hz = ghn[c + 32], hn = ghn[c + 64];
    float4 bir = bih4[c], biz = bih4[c + 32], bin = bih4[c + 64];
    float4 bhr = bhh4[c], bhz = bhh4[c + 32], bhn = bhh4[c + 64];
    float4 h = h4[idx];
    float4 o;
#define GRU1(X)                                                                 \
    {                                                                           \
        float r = 1.0f / (1.0f + __expf(-(ir.X + bir.X + hr.X + bhr.X)));       \
        float z = 1.0f / (1.0f + __expf(-(iz.X + biz.X + hz.X + bhz.X)));       \
        float nn = tanhf(in_.X + bin.X + r * (hn.X + bhn.X));                   \
        o.X = (1.0f - z) * nn + z * h.X;                                        \
    }
    GRU1(x) GRU1(y) GRU1(z) GRU1(w)
#undef GRU1
    h4[idx] = o;
    if (zero_agg) agg4[idx] = make_float4(0.f, 0.f, 0.f, 0.f);
}

// ---------------- per-graph mean pool (batch sorted) ----------------
__device__ __forceinline__ int lower_bound_dev(const int* a, int n, int key) {
    int lo = 0, hi = n;
    while (lo < hi) {
        int mid = (lo + hi) >> 1;
        if (a[mid] < key) lo = mid + 1; else hi = mid;
    }
    return lo;
}

__global__ void pool_kernel(const float* __restrict__ h,
                            const int* __restrict__ batch,
                            float* __restrict__ out, int N) {
    int g = blockIdx.x;
    int tid = threadIdx.x;
    int sub = tid >> 7;
    int d = tid & 127;
    __shared__ int s_lo, s_hi;
    __shared__ float sbuf[4][128];
    if (tid == 0) {
        s_lo = lower_bound_dev(batch, N, g);
        s_hi = lower_bound_dev(batch, N, g + 1);
    }
    __syncthreads();
    int lo = s_lo, hi = s_hi;
    float acc = 0.0f;
    for (int n = lo + sub; n < hi; n += 4)
        acc += h[(size_t)n * D + d];
    sbuf[sub][d] = acc;
    __syncthreads();
    if (sub == 0) {
        float total = sbuf[0][d] + sbuf[1][d] + sbuf[2][d] + sbuf[3][d];
        float cnt = (float)(hi - lo);
        out[(size_t)g * D + d] = total / fmaxf(cnt, 1.0f);
    }
}

// ---------------- launch ----------------
extern "C" void kernel_launch(void* const* d_in, const int* in_sizes, int n_in,
                              void* d_out, int out_size) {
    const int* node_ids = (const int*)d_in[0];
    const int* edge_index = (const int*)d_in[1];
    const int* batch = (const int*)d_in[2];
    const float* embed = (const float*)d_in[4];
    const float* conv_w = (const float*)d_in[5];
    const float* w_ih = (const float*)d_in[6];
    const float* w_hh = (const float*)d_in[7];
    const float* b_ih = (const float*)d_in[8];
    const float* b_hh = (const float*)d_in[9];
    float* out = (float*)d_out;

    int N = in_sizes[0];
    int E = in_sizes[1] / 2;
    int G = out_size / D;
    const int* src = edge_index;
    const int* dst = edge_index + E;

    float *h, *m, *agg, *gi, *gh, *convT;
    cudaGetSymbolAddress((void**)&h, g_h);
    cudaGetSymbolAddress((void**)&m, g_m);
    cudaGetSymbolAddress((void**)&agg, g_agg);
    cudaGetSymbolAddress((void**)&gi, g_gi);
    cudaGetSymbolAddress((void**)&gh, g_gh);
    cudaGetSymbolAddress((void**)&convT, g_convT);

    static int smem_set = 0;
    if (!smem_set) {
        cudaFuncSetAttribute(gemm_wmma, cudaFuncAttributeMaxDynamicSharedMemorySize,
                             SMEM_FLOATS * (int)sizeof(float));
        smem_set = 1;
    }

    conv_transpose_kernel<<<(2 * D * D + 255) / 256, 256>>>(conv_w, convT);
    gather_kernel<<<(N * 32 + 255) / 256, 256>>>(node_ids, (const float4*)embed,
                                                 (float4*)h, (float4*)agg, N);

    int rowBlocks = (N + 127) / 128;   // 391
    size_t smemBytes = SMEM_FLOATS * sizeof(float);

    for (int layer = 0; layer < 2; layer++) {
        // m = h @ conv_w[layer]
        gemm_wmma<<<dim3(1, rowBlocks), 256, smemBytes>>>(
            h, convT + (size_t)layer * D * D, m, N, D);

        // gh = h @ w_hh^T (independent of scatter; h hot in L2)
        gemm_wmma<<<dim3(3, rowBlocks), 256, smemBytes>>>(h, w_hh, gh, N, 3 * D);

        // agg[dst] += m[src]
        {
            int warpsPerBlock = 8;
            int blocks = (E + warpsPerBlock - 1) / warpsPerBlock;
            scatter_kernel<<<blocks, warpsPerBlock * 32>>>((const float4*)m, src, dst,
                                                           agg, E);
        }

        // gi = agg @ w_ih^T
        gemm_wmma<<<dim3(3, rowBlocks), 256, smemBytes>>>(agg, w_ih, gi, N, 3 * D);

        // h = GRU(gi, gh, h); zero agg for next layer's scatter
        gru_kernel<<<(N * 32 + 255) / 256, 256>>>((const float4*)gi,
                                                  (const float4*)gh,
                                                  (const float4*)b_ih,
                                                  (const float4*)b_hh,
                                                  (float4*)h, (float4*)agg,
                                                  N * 32, layer == 0 ? 1 : 0);
    }

    pool_kernel<<<G, 512>>>(h, batch, out, N);
}

// round 6
// speedup vs baseline: 1.1089x; 1.0010x over previous
#include <cuda_runtime.h>
#include <cuda_bf16.h>
#include <math.h>
#include <stdint.h>
#include <mma.h>

using namespace nvcuda;

#define D 128
#define MAXN 50000
#define NPAD 50048           // 391 * 128, row-padded so GEMM C stores need no guard
#define LDM 136              // padded smem leading dim

// ---------------- scratch ----------------
__device__ float g_h[NPAD * D];
__device__ float g_m[NPAD * D];
__device__ float g_agg[NPAD * D];
__device__ float g_gi[NPAD * 3 * D];
__device__ float g_gh[NPAD * 3 * D];
__device__ float g_convT[2 * D * D];   // conv_w transposed -> B operand [n][k]

// ================= wmma tf32 GEMM, software-pipelined =================
// C[N x M] = A[N x 128] @ B^T ; B is [M rows, 128 cols] K-major.
// CTA tile 128x128, 256 threads (8 warps as 2m x 4n), warp tile 64x32.
// C rows are UNGUARDED (buffers padded to NPAD); A rows ≥ N are zero-filled.
#define SMEM_FLOATS (2 * 128 * LDM)

__global__ __launch_bounds__(256, 1)
void gemm_wmma(const float* __restrict__ A, const float* __restrict__ Bw,
               float* __restrict__ C, int N, int M) {
    extern __shared__ float smem[];
    float* As = smem;               // [128][LDM]
    float* Bs = smem + 128 * LDM;   // [128][LDM], rows = output cols (n)

    int tid = threadIdx.x;
    int w = tid >> 5;
    int block_row = blockIdx.y * 128;
    int block_col = blockIdx.x * 128;

    // ---- stage tiles (fp32 -> tf32) ----
    {
        int r = tid >> 1;
        int kb = (tid & 1) * 64;
        bool va = (block_row + r) < N;
        const float4* arow = (const float4*)(A + (size_t)(block_row + r) * 128 + kb);
        const float4* brow = (const float4*)(Bw + (size_t)(block_col + r) * 128 + kb);
#pragma unroll
        for (int i = 0; i < 16; i++) {
            float4 x = va ? arow[i] : make_float4(0.f, 0.f, 0.f, 0.f);
            x.x = wmma::__float_to_tf32(x.x);
            x.y = wmma::__float_to_tf32(x.y);
            x.z = wmma::__float_to_tf32(x.z);
            x.w = wmma::__float_to_tf32(x.w);
            *(float4*)&As[r * LDM + kb + i * 4] = x;
            float4 y = brow[i];
            y.x = wmma::__float_to_tf32(y.x);
            y.y = wmma::__float_to_tf32(y.y);
            y.z = wmma::__float_to_tf32(y.z);
            y.w = wmma::__float_to_tf32(y.w);
            *(float4*)&Bs[r * LDM + kb + i * 4] = y;
        }
    }
    __syncthreads();

    int wm = w >> 2;   // 0..1
    int wn = w & 3;    // 0..3
    const float* aBase = &As[wm * 64 * LDM];
    const float* bBase = &Bs[wn * 32 * LDM];

    wmma::fragment<wmma::accumulator, 16, 16, 8, float> acc[4][2];
#pragma unroll
    for (int i = 0; i < 4; i++)
#pragma unroll
        for (int j = 0; j < 2; j++)
            wmma::fill_fragment(acc[i][j], 0.0f);

    // double-buffered fragments; fully unrolled so indices are compile-time
    wmma::fragment<wmma::matrix_a, 16, 16, 8, wmma::precision::tf32,
                   wmma::row_major> af[2][4];
    wmma::fragment<wmma::matrix_b, 16, 16, 8, wmma::precision::tf32,
                   wmma::col_major> bf[2][2];

#pragma unroll
    for (int i = 0; i < 4; i++)
        wmma::load_matrix_sync(af[0][i], aBase + (i * 16) * LDM, LDM);
#pragma unroll
    for (int j = 0; j < 2; j++)
        wmma::load_matrix_sync(bf[0][j], bBase + (j * 16) * LDM, LDM);

#pragma unroll
    for (int s = 0; s < 16; s++) {
        const int cur = s & 1;
        const int nxt = cur ^ 1;
        if (s < 15) {
            const int k = (s + 1) * 8;
#pragma unroll
            for (int i = 0; i < 4; i++)
                wmma::load_matrix_sync(af[nxt][i], aBase + (i * 16) * LDM + k, LDM);
#pragma unroll
            for (int j = 0; j < 2; j++)
                wmma::load_matrix_sync(bf[nxt][j], bBase + (j * 16) * LDM + k, LDM);
        }
#pragma unroll
        for (int i = 0; i < 4; i++)
#pragma unroll
            for (int j = 0; j < 2; j++)
                wmma::mma_sync(acc[i][j], af[cur][i], bf[cur][j], acc[i][j]);
    }

    // ---- direct store (C padded; no guard, no smem round-trip) ----
    float* cw = C + (size_t)(block_row + wm * 64) * M + block_col + wn * 32;
#pragma unroll
    for (int i = 0; i < 4; i++)
#pragma unroll
        for (int j = 0; j < 2; j++)
            wmma::store_matrix_sync(cw + (size_t)(i * 16) * M + j * 16, acc[i][j],
                                    M, wmma::mem_row_major);
}

// ---------------- conv weight transpose: BT[l][n][k] = W[l][k][n] ----------------
__global__ void conv_transpose_kernel(const float* __restrict__ W, float* __restrict__ BT) {
    int idx = blockIdx.x * blockDim.x + threadIdx.x;
    if (idx >= 2 * D * D) return;
    int l = idx / (D * D);
    int rem = idx % (D * D);
    int k = rem / D;
    int n = rem % D;
    BT[(size_t)l * D * D + (size_t)n * D + k] = W[idx];
}

// ---------------- gather: h = embed[node_ids]; also zero agg ----------------
__global__ void gather_kernel(const int* __restrict__ node_ids,
                              const float4* __restrict__ embed4,
                              float4* __restrict__ h4,
                              float4* __restrict__ agg4, int N) {
    int idx = blockIdx.x * blockDim.x + threadIdx.x;
    if (idx >= N * 32) return;
    int n = idx >> 5;
    int c = idx & 31;
    int id = node_ids[n];
    h4[(size_t)n * 32 + c] = embed4[(size_t)id * 32 + c];
    agg4[idx] = make_float4(0.f, 0.f, 0.f, 0.f);
}

// ---------------- edge scatter: agg[dst] += m[src], one warp per edge ----------------
__global__ void scatter_kernel(const float4* __restrict__ m4,
                               const int* __restrict__ src,
                               const int* __restrict__ dst,
                               float* __restrict__ agg, int E) {
    int e = blockIdx.x * (blockDim.x >> 5) + (threadIdx.x >> 5);
    int lane = threadIdx.x & 31;
    if (e >= E) return;
    int s = __ldg(&src[e]);
    int d = __ldg(&dst[e]);
    float4 v = m4[(size_t)s * 32 + lane];
    float* p = agg + (size_t)d * D + lane * 4;
    asm volatile("red.global.add.v4.f32 [%0], {%1, %2, %3, %4};"
                 :: "l"(p), "f"(v.x), "f"(v.y), "f"(v.z), "f"(v.w) : "memory");
}

// ---------------- GRU gate fusion; optionally zero agg for next layer ----------------
__global__ void gru_kernel(const float4* __restrict__ gi4,
                           const float4* __restrict__ gh4,
                           const float4* __restrict__ bih4,
                           const float4* __restrict__ bhh4,
                           float4* __restrict__ h4,
                           float4* __restrict__ agg4,
                           int total4, int zero_agg) {
    int idx = blockIdx.x * blockDim.x + threadIdx.x;
    if (idx >= total4) return;
    int n = idx >> 5;
    int c = idx & 31;
    const float4* gin = gi4 + (size_t)n * 96;
    const float4* ghn = gh4 + (size_t)n * 96;
    float4 ir = gin[c], iz = gin[c + 32], in_ = gin[c + 64];
    float4 hr = ghn[c], hz = ghn[c + 32], hn = ghn[c + 64];
    float4 bir = bih4[c], biz = bih4[c + 32], bin = bih4[c + 64];
    float4 bhr = bhh4[c], bhz = bhh4[c + 32], bhn = bhh4[c + 64];
    float4 h = h4[idx];
    float4 o;
#define GRU1(X)                                                                 \
    {                                                                           \
        float r = 1.0f / (1.0f + __expf(-(ir.X + bir.X + hr.X + bhr.X)));       \
        float z = 1.0f / (1.0f + __expf(-(iz.X + biz.X + hz.X + bhz.X)));       \
        float nn = tanhf(in_.X + bin.X + r * (hn.X + bhn.X));                   \
        o.X = (1.0f - z) * nn + z * h.X;                                        \
    }
    GRU1(x) GRU1(y) GRU1(z) GRU1(w)
#undef GRU1
    h4[idx] = o;
    if (zero_agg) agg4[idx] = make_float4(0.f, 0.f, 0.f, 0.f);
}

// ---------------- per-graph mean pool (batch sorted) ----------------
__device__ __forceinline__ int lower_bound_dev(const int* a, int n, int key) {
    int lo = 0, hi = n;
    while (lo < hi) {
        int mid = (lo + hi) >> 1;
        if (a[mid] < key) lo = mid + 1; else hi = mid;
    }
    return lo;
}

__global__ void pool_kernel(const float* __restrict__ h,
                            const int* __restrict__ batch,
                            float* __restrict__ out, int N) {
    int g = blockIdx.x;
    int tid = threadIdx.x;
    int sub = tid >> 7;
    int d = tid & 127;
    __shared__ int s_lo, s_hi;
    __shared__ float sbuf[4][128];
    if (tid == 0) {
        s_lo = lower_bound_dev(batch, N, g);
        s_hi = lower_bound_dev(batch, N, g + 1);
    }
    __syncthreads();
    int lo = s_lo, hi = s_hi;
    float acc = 0.0f;
    for (int n = lo + sub; n < hi; n += 4)
        acc += h[(size_t)n * D + d];
    sbuf[sub][d] = acc;
    __syncthreads();
    if (sub == 0) {
        float total = sbuf[0][d] + sbuf[1][d] + sbuf[2][d] + sbuf[3][d];
        float cnt = (float)(hi - lo);
        out[(size_t)g * D + d] = total / fmaxf(cnt, 1.0f);
    }
}

// ---------------- launch ----------------
extern "C" void kernel_launch(void* const* d_in, const int* in_sizes, int n_in,
                              void* d_out, int out_size) {
    const int* node_ids = (const int*)d_in[0];
    const int* edge_index = (const int*)d_in[1];
    const int* batch = (const int*)d_in[2];
    const float* embed = (const float*)d_in[4];
    const float* conv_w = (const float*)d_in[5];
    const float* w_ih = (const float*)d_in[6];
    const float* w_hh = (const float*)d_in[7];
    const float* b_ih = (const float*)d_in[8];
    const float* b_hh = (const float*)d_in[9];
    float* out = (float*)d_out;

    int N = in_sizes[0];
    int E = in_sizes[1] / 2;
    int G = out_size / D;
    const int* src = edge_index;
    const int* dst = edge_index + E;

    float *h, *m, *agg, *gi, *gh, *convT;
    cudaGetSymbolAddress((void**)&h, g_h);
    cudaGetSymbolAddress((void**)&m, g_m);
    cudaGetSymbolAddress((void**)&agg, g_agg);
    cudaGetSymbolAddress((void**)&gi, g_gi);
    cudaGetSymbolAddress((void**)&gh, g_gh);
    cudaGetSymbolAddress((void**)&convT, g_convT);

    static int smem_set = 0;
    if (!smem_set) {
        cudaFuncSetAttribute(gemm_wmma, cudaFuncAttributeMaxDynamicSharedMemorySize,
                             SMEM_FLOATS * (int)sizeof(float));
        smem_set = 1;
    }

    conv_transpose_kernel<<<(2 * D * D + 255) / 256, 256>>>(conv_w, convT);
    gather_kernel<<<(N * 32 + 255) / 256, 256>>>(node_ids, (const float4*)embed,
                                                 (float4*)h, (float4*)agg, N);

    int rowBlocks = (N + 127) / 128;   // 391
    size_t smemBytes = SMEM_FLOATS * sizeof(float);

    for (int layer = 0; layer < 2; layer++) {
        // m = h @ conv_w[layer]
        gemm_wmma<<<dim3(1, rowBlocks), 256, smemBytes>>>(
            h, convT + (size_t)layer * D * D, m, N, D);

        // gh = h @ w_hh^T (independent of scatter; h hot in L2)
        gemm_wmma<<<dim3(3, rowBlocks), 256, smemBytes>>>(h, w_hh, gh, N, 3 * D);

        // agg[dst] += m[src]
        {
            int warpsPerBlock = 8;
            int blocks = (E + warpsPerBlock - 1) / warpsPerBlock;
            scatter_kernel<<<blocks, warpsPerBlock * 32>>>((const float4*)m, src, dst,
                                                           agg, E);
        }

        // gi = agg @ w_ih^T
        gemm_wmma<<<dim3(3, rowBlocks), 256, smemBytes>>>(agg, w_ih, gi, N, 3 * D);

        // h = GRU(gi, gh, h); zero agg for next layer's scatter
        gru_kernel<<<(N * 32 + 255) / 256, 256>>>((const float4*)gi,
                                                  (const float4*)gh,
                                                  (const float4*)b_ih,
                                                  (const float4*)b_hh,
                                                  (float4*)h, (float4*)agg,
                                                  N * 32, layer == 0 ? 1 : 0);
    }

    pool_kernel<<<G, 512>>>(h, batch, out, N);
}